// round 4
// baseline (speedup 1.0000x reference)
#include <cuda_runtime.h>
#include <cuda_bf16.h>
#include <math.h>

#define N_NODES 50000
#define N_EDGES 800000
#define F_IN    300
#define HID     128
#define HEADS   4
#define PER_H   32
#define NCLS    9

// ---------------- scratch (device globals; no allocation) ----------------
__device__ int   g_is64;
__device__ int   g_deg[N_NODES];
__device__ int   g_cursor[N_NODES];
__device__ int   g_rowstart[N_NODES + 1];
__device__ int   g_adj_src[N_EDGES];

__device__ float g_A[(size_t)N_NODES * HID];   // gemm output (pre-agg h)
__device__ float g_B[(size_t)N_NODES * HID];   // agg output (post-elu)
__device__ float g_as[(size_t)N_NODES * HEADS];
__device__ float g_ad[(size_t)N_NODES * HEADS];
__device__ float g_h3[(size_t)N_NODES * 12];   // layer3 h padded to 12
__device__ float g_a3s[N_NODES];
__device__ float g_a3d[N_NODES];

// ---------------- edge index decode (int32 vs int64 autodetect) ----------------
// If the buffer is int64, the high 32 bits of every value (< 2^32) are zero.
// Sampling 4096 pairs (32 KB) is safe under both interpretations.
__global__ void detect_kernel(const void* ei) {
    __shared__ int any;
    if (threadIdx.x == 0) any = 0;
    __syncthreads();
    const int* p = (const int*)ei;
    for (int i = threadIdx.x; i < 4096; i += 256) {
        if (p[2 * i + 1] != 0) any = 1;
    }
    __syncthreads();
    if (threadIdx.x == 0) g_is64 = (any == 0) ? 1 : 0;
}

__device__ __forceinline__ int edge_src(const void* ei, int e, int is64) {
    if (is64) return (int)((const long long*)ei)[e];
    return ((const int*)ei)[e];
}
__device__ __forceinline__ int edge_dst(const void* ei, int e, int is64) {
    if (is64) return (int)((const long long*)ei)[N_EDGES + e];
    return ((const int*)ei)[N_EDGES + e];
}

// ---------------- CSR build ----------------
__global__ void zero_kernel() {
    int i = blockIdx.x * blockDim.x + threadIdx.x;
    if (i < N_NODES) { g_deg[i] = 0; g_cursor[i] = 0; }
}

__global__ void count_kernel(const void* __restrict__ ei) {
    int e = blockIdx.x * blockDim.x + threadIdx.x;
    int is64 = g_is64;
    if (e < N_EDGES) {
        int dst = edge_dst(ei, e, is64);
        if ((unsigned)dst < (unsigned)N_NODES)   // safety: never write OOB
            atomicAdd(&g_deg[dst], 1);
    }
}

__global__ void scan_kernel() {
    __shared__ int wsum[32];
    __shared__ int carry_s;
    int t = threadIdx.x, lane = t & 31, warp = t >> 5;
    if (t == 0) { carry_s = 0; g_rowstart[0] = 0; }
    __syncthreads();
    for (int base = 0; base < N_NODES; base += 1024) {
        __syncthreads();
        int carry = carry_s;
        int i = base + t;
        int v = (i < N_NODES) ? g_deg[i] : 0;
        int x = v;
        #pragma unroll
        for (int off = 1; off < 32; off <<= 1) {
            int y = __shfl_up_sync(0xffffffffu, x, off);
            if (lane >= off) x += y;
        }
        if (lane == 31) wsum[warp] = x;
        __syncthreads();
        if (warp == 0) {
            int wv = wsum[lane];
            #pragma unroll
            for (int off = 1; off < 32; off <<= 1) {
                int y = __shfl_up_sync(0xffffffffu, wv, off);
                if (lane >= off) wv += y;
            }
            wsum[lane] = wv;
        }
        __syncthreads();
        int pre = (warp > 0) ? wsum[warp - 1] : 0;
        if (i < N_NODES) g_rowstart[i + 1] = carry + pre + x;
        __syncthreads();
        if (t == 0) carry_s = carry + wsum[31];
    }
}

__global__ void fill_kernel(const void* __restrict__ ei) {
    int e = blockIdx.x * blockDim.x + threadIdx.x;
    int is64 = g_is64;
    if (e < N_EDGES) {
        int dst = edge_dst(ei, e, is64);
        int src = edge_src(ei, e, is64);
        if ((unsigned)dst < (unsigned)N_NODES &&
            (unsigned)src < (unsigned)N_NODES) {   // safety: never write OOB
            int pos = atomicAdd(&g_cursor[dst], 1);
            int slot = g_rowstart[dst] + pos;
            if ((unsigned)slot < (unsigned)N_EDGES)
                g_adj_src[slot] = src;
        }
    }
}

// ---------------- GEMM: C[M,128] = A[M,K] @ W[K,128]  (no bias) ----------------
// 64x128 tile, 256 threads, micro-tile 8 rows x 4 cols per thread.
__global__ void gemm128_kernel(const float* __restrict__ Ain, const float* __restrict__ W,
                               int M, int K) {
    __shared__ float As[8][64];
    __shared__ float Ws[8][128];
    const float* A = (Ain != nullptr) ? Ain : g_B;
    float* C = g_A;
    int t = threadIdx.x;
    int row0 = blockIdx.x * 64;
    int col = (t & 31) * 4;
    int rowblk = t >> 5;
    float acc[8][4];
    #pragma unroll
    for (int r = 0; r < 8; r++)
        #pragma unroll
        for (int j = 0; j < 4; j++) acc[r][j] = 0.f;

    for (int k0 = 0; k0 < K; k0 += 8) {
        #pragma unroll
        for (int i = 0; i < 2; i++) {
            int idx = t * 2 + i;
            int m = idx >> 3;
            int kk = idx & 7;
            int gm = row0 + m, gk = k0 + kk;
            As[kk][m] = (gm < M && gk < K) ? A[(size_t)gm * K + gk] : 0.f;
        }
        {
            int idx = t * 4;
            int kk = idx >> 7;
            int c = idx & 127;
            int gk = k0 + kk;
            float4 w = (gk < K) ? *(const float4*)&W[(size_t)gk * 128 + c]
                                : make_float4(0.f, 0.f, 0.f, 0.f);
            Ws[kk][c + 0] = w.x; Ws[kk][c + 1] = w.y;
            Ws[kk][c + 2] = w.z; Ws[kk][c + 3] = w.w;
        }
        __syncthreads();
        #pragma unroll
        for (int kk = 0; kk < 8; kk++) {
            float4 w = *(const float4*)&Ws[kk][col];
            #pragma unroll
            for (int r = 0; r < 8; r++) {
                float a = As[kk][rowblk + r * 8];
                acc[r][0] += a * w.x;
                acc[r][1] += a * w.y;
                acc[r][2] += a * w.z;
                acc[r][3] += a * w.w;
            }
        }
        __syncthreads();
    }
    #pragma unroll
    for (int r = 0; r < 8; r++) {
        int gm = row0 + rowblk + r * 8;
        if (gm < M) {
            float4 v = make_float4(acc[r][0], acc[r][1], acc[r][2], acc[r][3]);
            *(float4*)&C[(size_t)gm * 128 + col] = v;
        }
    }
}

// ---------------- attention logits: a_src/a_dst per (node, head) ----------------
__global__ void attn_kernel(const float* __restrict__ att_s, const float* __restrict__ att_d) {
    int n = blockIdx.x;
    int t = threadIdx.x;          // 128
    int head = t >> 5, lane = t & 31;
    float v = g_A[(size_t)n * 128 + t];
    float ps = v * att_s[t];
    float pd = v * att_d[t];
    #pragma unroll
    for (int off = 16; off; off >>= 1) {
        ps += __shfl_xor_sync(0xffffffffu, ps, off);
        pd += __shfl_xor_sync(0xffffffffu, pd, off);
    }
    if (lane == 0) {
        g_as[n * HEADS + head] = ps;
        g_ad[n * HEADS + head] = pd;
    }
}

// ---------------- aggregation (128-wide layers), warp per node ----------------
__global__ void agg128_kernel(const float* __restrict__ bias) {
    int t = threadIdx.x;
    int warp = t >> 5, lane = t & 31;
    int n = blockIdx.x * 8 + warp;
    if (n >= N_NODES) return;

    const float* h = g_A;
    float adh = g_ad[n * HEADS + (lane & 3)];
    int s0 = g_rowstart[n], s1 = g_rowstart[n + 1];

    float acc0 = 0.f, acc1 = 0.f, acc2 = 0.f, acc3 = 0.f;
    float ws0 = 0.f, ws1 = 0.f, ws2 = 0.f, ws3 = 0.f;

    for (int base = s0; base < s1; base += 32) {
        int nvalid = min(32, s1 - base);
        int s = (base + lane < s1) ? g_adj_src[base + lane] : 0;
        #pragma unroll
        for (int g = 0; g < 4; g++) {
            int eoff = g * 8 + (lane >> 2);
            int head = lane & 3;
            int esrc = __shfl_sync(0xffffffffu, s, eoff);
            float w = 0.f;
            if (eoff < nvalid) {
                float e = g_as[esrc * HEADS + head] + adh;
                e = (e > 0.f) ? e : 0.2f * e;
                w = __expf(e);
            }
            #pragma unroll
            for (int j = 0; j < 8; j++) {
                int idx = g * 8 + j;
                if (idx >= nvalid) break;
                int ss = __shfl_sync(0xffffffffu, s, idx);
                float w0 = __shfl_sync(0xffffffffu, w, j * 4 + 0);
                float w1 = __shfl_sync(0xffffffffu, w, j * 4 + 1);
                float w2 = __shfl_sync(0xffffffffu, w, j * 4 + 2);
                float w3 = __shfl_sync(0xffffffffu, w, j * 4 + 3);
                const float* row = h + (size_t)ss * 128;
                acc0 += w0 * row[lane];
                acc1 += w1 * row[32 + lane];
                acc2 += w2 * row[64 + lane];
                acc3 += w3 * row[96 + lane];
                ws0 += w0; ws1 += w1; ws2 += w2; ws3 += w3;
            }
        }
    }
    float o0 = (ws0 > 0.f) ? acc0 / ws0 : 0.f;
    float o1 = (ws1 > 0.f) ? acc1 / ws1 : 0.f;
    float o2 = (ws2 > 0.f) ? acc2 / ws2 : 0.f;
    float o3 = (ws3 > 0.f) ? acc3 / ws3 : 0.f;
    o0 += bias[lane];       o1 += bias[32 + lane];
    o2 += bias[64 + lane];  o3 += bias[96 + lane];
    o0 = (o0 > 0.f) ? o0 : expm1f(o0);
    o1 = (o1 > 0.f) ? o1 : expm1f(o1);
    o2 = (o2 > 0.f) ? o2 : expm1f(o2);
    o3 = (o3 > 0.f) ? o3 : expm1f(o3);
    float* out = g_B + (size_t)n * 128;
    out[lane] = o0; out[32 + lane] = o1; out[64 + lane] = o2; out[96 + lane] = o3;
}

// ---------------- layer 3 GEMM (128->9, padded 12) fused with attn dots ----------------
__global__ void gemm3_kernel(const float* __restrict__ W3, const float* __restrict__ as3,
                             const float* __restrict__ ad3) {
    __shared__ float Ws[128 * 12];
    int t = threadIdx.x;   // 256
    for (int i = t; i < 128 * 12; i += 256) {
        int k = i / 12, c = i % 12;
        Ws[i] = (c < NCLS) ? W3[k * NCLS + c] : 0.f;
    }
    __syncthreads();
    int warp = t >> 5, lane = t & 31;
    int n = blockIdx.x * 8 + warp;
    if (n >= N_NODES) return;
    float acc[12];
    #pragma unroll
    for (int c = 0; c < 12; c++) acc[c] = 0.f;
    const float* xr = g_B + (size_t)n * 128;
    #pragma unroll
    for (int kk = 0; kk < 4; kk++) {
        int k = lane + kk * 32;
        float xv = xr[k];
        #pragma unroll
        for (int c = 0; c < 12; c++) acc[c] += xv * Ws[k * 12 + c];
    }
    #pragma unroll
    for (int off = 16; off; off >>= 1)
        #pragma unroll
        for (int c = 0; c < 12; c++) acc[c] += __shfl_xor_sync(0xffffffffu, acc[c], off);
    if (lane == 0) {
        float s = 0.f, d = 0.f;
        #pragma unroll
        for (int c = 0; c < NCLS; c++) { s += acc[c] * as3[c]; d += acc[c] * ad3[c]; }
        g_a3s[n] = s;
        g_a3d[n] = d;
        float* hr = g_h3 + (size_t)n * 12;
        #pragma unroll
        for (int c = 0; c < 12; c++) hr[c] = acc[c];
    }
}

// ---------------- layer 3 aggregation + bias + elu + log_softmax ----------------
__global__ void agg3_kernel(const float* __restrict__ b3, float* __restrict__ out) {
    int t = threadIdx.x;
    int warp = t >> 5, lane = t & 31;
    int n = blockIdx.x * 8 + warp;
    if (n >= N_NODES) return;
    float ad = g_a3d[n];
    int s0 = g_rowstart[n], s1 = g_rowstart[n + 1];
    float4 A0 = make_float4(0, 0, 0, 0), A1 = A0, A2 = A0;
    float ws = 0.f;
    for (int i = s0 + lane; i < s1; i += 32) {
        int s = g_adj_src[i];
        float e = g_a3s[s] + ad;
        e = (e > 0.f) ? e : 0.2f * e;
        float w = __expf(e);
        ws += w;
        const float4* r = (const float4*)(g_h3 + (size_t)s * 12);
        float4 r0 = r[0], r1 = r[1], r2 = r[2];
        A0.x += w * r0.x; A0.y += w * r0.y; A0.z += w * r0.z; A0.w += w * r0.w;
        A1.x += w * r1.x; A1.y += w * r1.y; A1.z += w * r1.z; A1.w += w * r1.w;
        A2.x += w * r2.x;
    }
    #pragma unroll
    for (int off = 16; off; off >>= 1) {
        A0.x += __shfl_xor_sync(0xffffffffu, A0.x, off);
        A0.y += __shfl_xor_sync(0xffffffffu, A0.y, off);
        A0.z += __shfl_xor_sync(0xffffffffu, A0.z, off);
        A0.w += __shfl_xor_sync(0xffffffffu, A0.w, off);
        A1.x += __shfl_xor_sync(0xffffffffu, A1.x, off);
        A1.y += __shfl_xor_sync(0xffffffffu, A1.y, off);
        A1.z += __shfl_xor_sync(0xffffffffu, A1.z, off);
        A1.w += __shfl_xor_sync(0xffffffffu, A1.w, off);
        A2.x += __shfl_xor_sync(0xffffffffu, A2.x, off);
        ws += __shfl_xor_sync(0xffffffffu, ws, off);
    }
    if (lane == 0) {
        float inv = (ws > 0.f) ? 1.f / ws : 0.f;
        float v[9];
        v[0] = A0.x * inv; v[1] = A0.y * inv; v[2] = A0.z * inv; v[3] = A0.w * inv;
        v[4] = A1.x * inv; v[5] = A1.y * inv; v[6] = A1.z * inv; v[7] = A1.w * inv;
        v[8] = A2.x * inv;
        float m = -1e30f;
        #pragma unroll
        for (int c = 0; c < 9; c++) {
            v[c] += b3[c];
            v[c] = (v[c] > 0.f) ? v[c] : expm1f(v[c]);
            m = fmaxf(m, v[c]);
        }
        float se = 0.f;
        #pragma unroll
        for (int c = 0; c < 9; c++) se += __expf(v[c] - m);
        float l = logf(se);
        float* o = out + (size_t)n * 9;
        #pragma unroll
        for (int c = 0; c < 9; c++) o[c] = v[c] - m - l;
    }
}

// ---------------- launch ----------------
extern "C" void kernel_launch(void* const* d_in, const int* in_sizes, int n_in,
                              void* d_out, int out_size) {
    const float* x   = (const float*)d_in[0];
    const void*  ei  = d_in[1];
    const float* W1  = (const float*)d_in[2];
    const float* as1 = (const float*)d_in[3];
    const float* ad1 = (const float*)d_in[4];
    const float* b1  = (const float*)d_in[5];
    const float* W2  = (const float*)d_in[6];
    const float* as2 = (const float*)d_in[7];
    const float* ad2 = (const float*)d_in[8];
    const float* b2  = (const float*)d_in[9];
    const float* W3  = (const float*)d_in[10];
    const float* as3 = (const float*)d_in[11];
    const float* ad3 = (const float*)d_in[12];
    const float* b3  = (const float*)d_in[13];
    float* out = (float*)d_out;

    const int EB = (N_EDGES + 255) / 256;
    const int NB = (N_NODES + 255) / 256;
    const int WB = (N_NODES + 7) / 8;      // warp-per-node grids
    const int GB = (N_NODES + 63) / 64;    // gemm tiles

    // CSR build (per-launch, deterministic work)
    detect_kernel<<<1, 256>>>(ei);
    zero_kernel<<<NB, 256>>>();
    count_kernel<<<EB, 256>>>(ei);
    scan_kernel<<<1, 1024>>>();
    fill_kernel<<<EB, 256>>>(ei);

    // layer 1
    gemm128_kernel<<<GB, 256>>>(x, W1, N_NODES, F_IN);
    attn_kernel<<<N_NODES, 128>>>(as1, ad1);
    agg128_kernel<<<WB, 256>>>(b1);

    // layer 2
    gemm128_kernel<<<GB, 256>>>(nullptr, W2, N_NODES, HID);
    attn_kernel<<<N_NODES, 128>>>(as2, ad2);
    agg128_kernel<<<WB, 256>>>(b2);

    // layer 3
    gemm3_kernel<<<WB, 256>>>(W3, as3, ad3);
    agg3_kernel<<<WB, 256>>>(b3, out);
}